// round 6
// baseline (speedup 1.0000x reference)
#include <cuda_runtime.h>
#include <cuda_bf16.h>
#include <math.h>
#include <stdint.h>

#define BN   8
#define CIN  32
#define COUT 32
#define HW   384
#define AUX  128
#define HID  256
#define MODOUT (COUT*CIN*9)   // 9216
#define KDIM 288              // k = tap*32 + ci
#define WST  296              // padded W row stride (conflict-free ldmatrix)

// Scratch (allocation-free rule: __device__ globals)
__device__ float g_bias[BN * COUT];
__device__ __nv_bfloat16 g_wh[BN * COUT * KDIM];  // [n][co][tap*32+ci] hi
__device__ __nv_bfloat16 g_wl[BN * COUT * KDIM];  // lo

// ---------------------------------------------------------------------------
// warp-MMA helpers (sm_80-class, valid on compute_103 without 'a')
// ---------------------------------------------------------------------------
__device__ __forceinline__ uint32_t smem_u32(const void* p) {
    uint32_t a;
    asm("{ .reg .u64 t; cvta.to.shared.u64 t, %1; cvt.u32.u64 %0, t; }"
        : "=r"(a) : "l"(p));
    return a;
}
__device__ __forceinline__ void ldm4(uint32_t r[4], uint32_t addr) {
    asm volatile("ldmatrix.sync.aligned.m8n8.x4.shared.b16 {%0,%1,%2,%3}, [%4];"
        : "=r"(r[0]), "=r"(r[1]), "=r"(r[2]), "=r"(r[3]) : "r"(addr));
}
__device__ __forceinline__ void mma_bf16(float d[4], const uint32_t a[4],
                                         const uint32_t b[2]) {
    asm volatile("mma.sync.aligned.m16n8k16.row.col.f32.bf16.bf16.f32 "
        "{%0,%1,%2,%3}, {%4,%5,%6,%7}, {%8,%9}, {%0,%1,%2,%3};"
        : "+f"(d[0]), "+f"(d[1]), "+f"(d[2]), "+f"(d[3])
        : "r"(a[0]), "r"(a[1]), "r"(a[2]), "r"(a[3]), "r"(b[0]), "r"(b[1]));
}
// pack two fp32 -> bf16x2 (lo = a, hi = b)
__device__ __forceinline__ uint32_t bf2pack(float a, float b) {
    uint32_t r;
    asm("cvt.rn.satfinite.bf16x2.f32 %0, %1, %2;" : "=r"(r) : "f"(b), "f"(a));
    return r;
}

// ---------------------------------------------------------------------------
// Fused MLP: grid 37. Blocks 0..35: 256 mod outputs x all 8 samples
// (fc_w2 read ONCE). Block 36: biases for all samples.
// ---------------------------------------------------------------------------
__global__ void mlp_fused(const float* __restrict__ y,
                          const float* __restrict__ weight,
                          const float* __restrict__ fc_w1, const float* __restrict__ fc_b1,
                          const float* __restrict__ fc_a_p,
                          const float* __restrict__ fc_w2, const float* __restrict__ fc_b2,
                          const float* __restrict__ b_w1,  const float* __restrict__ b_b1,
                          const float* __restrict__ b_a_p,
                          const float* __restrict__ b_w2,  const float* __restrict__ b_b2)
{
    __shared__ float y_s[BN * AUX];
    __shared__ float h_s[BN * HID];
    const int t = threadIdx.x;

    #pragma unroll
    for (int i = t; i < BN*AUX; i += 256) y_s[i] = y[i];
    __syncthreads();

    if (blockIdx.x < 36) {
        // ---- hidden layer, all 8 samples (8-way ILP) ----
        {
            float hacc[BN] = {0,0,0,0,0,0,0,0};
            #pragma unroll 4
            for (int i = 0; i < AUX; i++) {
                const float wv = fc_w1[i*HID + t];
                #pragma unroll
                for (int n = 0; n < BN; n++)
                    hacc[n] = fmaf(y_s[n*AUX + i], wv, hacc[n]);
            }
            const float a = *fc_a_p;
            const float b1v = fc_b1[t];
            #pragma unroll
            for (int n = 0; n < BN; n++) {
                const float h = hacc[n] + b1v;
                h_s[n*HID + t] = (h >= 0.f) ? h : a*h;
            }
        }
        __syncthreads();

        const int j = blockIdx.x * 256 + t;   // j = co*288 + ci*9 + tap
        float acc[BN] = {0,0,0,0,0,0,0,0};
        #pragma unroll 8
        for (int hh = 0; hh < HID; hh++) {
            const float wv = fc_w2[hh*MODOUT + j];
            #pragma unroll
            for (int n = 0; n < BN; n++)
                acc[n] = fmaf(h_s[n*HID + hh], wv, acc[n]);
        }
        const float wj = weight[j];
        const float b2 = fc_b2[j];
        const int co  = j / 288;
        const int r   = j - co*288;
        const int ci  = r / 9;
        const int tap = r - ci*9;
        const int kk  = tap*32 + ci;
        #pragma unroll
        for (int n = 0; n < BN; n++) {
            const float m  = acc[n] + b2;
            const float sg = 1.f / (1.f + expf(-m));
            const float wm = sg * wj;
            __nv_bfloat16 hi = __float2bfloat16(wm);
            __nv_bfloat16 lo = __float2bfloat16(wm - __bfloat162float(hi));
            const int o = (n*COUT + co)*KDIM + kk;
            g_wh[o] = hi;
            g_wl[o] = lo;
        }
    } else {
        // ---- bias branch ----
        {
            float hacc[BN] = {0,0,0,0,0,0,0,0};
            #pragma unroll 4
            for (int i = 0; i < AUX; i++) {
                const float wv = b_w1[i*HID + t];
                #pragma unroll
                for (int n = 0; n < BN; n++)
                    hacc[n] = fmaf(y_s[n*AUX + i], wv, hacc[n]);
            }
            const float a = *b_a_p;
            const float b1v = b_b1[t];
            #pragma unroll
            for (int n = 0; n < BN; n++) {
                const float h = hacc[n] + b1v;
                h_s[n*HID + t] = (h >= 0.f) ? h : a*h;
            }
        }
        __syncthreads();

        const int n  = t >> 5;
        const int co = t & 31;
        const float* hb = h_s + n*HID;
        float m0 = 0.f, m1 = 0.f, m2 = 0.f, m3 = 0.f;
        #pragma unroll 4
        for (int hh = 0; hh < HID; hh += 4) {
            m0 = fmaf(hb[hh+0], b_w2[(hh+0)*COUT + co], m0);
            m1 = fmaf(hb[hh+1], b_w2[(hh+1)*COUT + co], m1);
            m2 = fmaf(hb[hh+2], b_w2[(hh+2)*COUT + co], m2);
            m3 = fmaf(hb[hh+3], b_w2[(hh+3)*COUT + co], m3);
        }
        g_bias[n*COUT + co] = (m0 + m1) + (m2 + m3) + b_b2[co];
    }
}

// ---------------------------------------------------------------------------
// Conv: mma.sync bf16 implicit GEMM, 3-pass hi/lo, 2-ROW OUTPUT BLOCKING.
// CTA: 384 threads (12 warps), 192-px tile, strip of 10/12 rows, 1 CTA/SM.
// Slab: 6-slot rolling window [slot][col(194)][ci pad 40] per hi/lo array.
// Per 2-row step: rolling A-chunk buffers amortize ldmatrix 2x; B-frags
// shared between the two rows via input-row (d) loop.
// ---------------------------------------------------------------------------
#define RC       194
#define CIP      40
#define NSLOT    6
#define SLAB_B   (NSLOT*RC*CIP*2)          // 93120 per array
#define W_BYTES  (COUT*WST*2)              // 18944
#define OFF_WH   0
#define OFF_WL   (W_BYTES)                 // 18944
#define OFF_XH   (2*W_BYTES)               // 37888
#define OFF_XL   (OFF_XH + SLAB_B)         // 131008
#define CONV_SMEM (OFF_XL + SLAB_B)        // 224128

__device__ __forceinline__ void stage_row(const float* __restrict__ xn,
                                          uint32_t* __restrict__ xh32,
                                          uint32_t* __restrict__ xl32,
                                          int gy, int x0, int tid)
{
    const int slot = (gy + 6) % 6;
    const bool yok = (unsigned)gy < (unsigned)HW;
    for (int i = tid; i < 16*RC; i += 384) {      // ci-pair x col
        const int cp  = i / RC;
        const int col = i - cp*RC;
        const int gx  = x0 - 1 + col;
        float f0 = 0.f, f1 = 0.f;
        if (yok && (unsigned)gx < (unsigned)HW) {
            const float* p = xn + ((2*cp)*HW + gy)*HW + gx;
            f0 = p[0];
            f1 = p[HW*HW];
        }
        const uint32_t h = bf2pack(f0, f1);
        const float f0h = __uint_as_float(h << 16);
        const float f1h = __uint_as_float(h & 0xFFFF0000u);
        const uint32_t l = bf2pack(f0 - f0h, f1 - f1h);
        const int o = (slot*RC + col)*(CIP/2) + cp;
        xh32[o] = h;
        xl32[o] = l;
    }
}

__global__ void __launch_bounds__(384, 1)
conv_mma(const float* __restrict__ x, float* __restrict__ out)
{
    extern __shared__ char smem[];
    uint16_t* xh16 = reinterpret_cast<uint16_t*>(smem + OFF_XH);
    uint16_t* xl16 = reinterpret_cast<uint16_t*>(smem + OFF_XL);
    uint32_t* xh32 = reinterpret_cast<uint32_t*>(smem + OFF_XH);
    uint32_t* xl32 = reinterpret_cast<uint32_t*>(smem + OFF_XL);

    const int tid  = threadIdx.x;
    const int lane = tid & 31;
    const int w    = tid >> 5;
    const int n    = blockIdx.y;
    const int st   = blockIdx.x >> 1;           // strip 0..36
    const int xt   = blockIdx.x & 1;
    const int x0   = xt * 192;
    const int row0  = (st < 7) ? st*12 : 84 + (st-7)*10;
    const int pairs = (st < 7) ? 6 : 5;

    // ---- per-sample weights -> padded smem (vectorized u32) ----
    {
        const uint32_t* gh = reinterpret_cast<const uint32_t*>(g_wh + (size_t)n*MODOUT);
        const uint32_t* gl = reinterpret_cast<const uint32_t*>(g_wl + (size_t)n*MODOUT);
        uint32_t* whs = reinterpret_cast<uint32_t*>(smem + OFF_WH);
        uint32_t* wls = reinterpret_cast<uint32_t*>(smem + OFF_WL);
        for (int i = tid; i < COUT*(KDIM/2); i += 384) {
            const int co = i / 144, k2 = i - co*144;
            whs[co*(WST/2) + k2] = gh[i];
            wls[co*(WST/2) + k2] = gl[i];
        }
    }
    const int lanehi = lane >> 2;
    const int laneq2 = (lane & 3) * 2;
    const float bias0 = g_bias[n*COUT + lanehi];
    const float bias1 = g_bias[n*COUT + lanehi + 8];
    const float bias2 = g_bias[n*COUT + lanehi + 16];
    const float bias3 = g_bias[n*COUT + lanehi + 24];

    const float* xn = x + (size_t)n * CIN * HW * HW;
    stage_row(xn, xh32, xl32, row0 - 1, x0, tid);
    stage_row(xn, xh32, xl32, row0,     x0, tid);
    stage_row(xn, xh32, xl32, row0 + 1, x0, tid);
    stage_row(xn, xh32, xl32, row0 + 2, x0, tid);
    __syncthreads();

    const uint32_t sb   = smem_u32(smem);
    const uint32_t aoff = (uint32_t)(((lane & 15)*WST + (lane >> 4)*8) * 2);
    const uint32_t whb  = sb + OFF_WH + aoff;
    const uint32_t wlb  = sb + OFF_WL + aoff;
    const int colb = w*16 + lanehi;

#define ALOAD(b, kh) do { \
    const uint32_t c32 = (uint32_t)(((kh)*3 + kw)*2 + half) * 32u; \
    ldm4(aH[b][0], whb + c32); ldm4(aH[b][1], whb + c32 + 16*WST*2); \
    ldm4(aL[b][0], wlb + c32); ldm4(aL[b][1], wlb + c32 + 16*WST*2); \
} while (0)

#define BLOAD(dd) do { \
    const int o = (s_[dd]*RC + colb + kw)*CIP + hoff + laneq2; \
    B0H[0] = *reinterpret_cast<const uint32_t*>(xh16 + o); \
    B0H[1] = *reinterpret_cast<const uint32_t*>(xh16 + o + 8); \
    B1H[0] = *reinterpret_cast<const uint32_t*>(xh16 + o + 8*CIP); \
    B1H[1] = *reinterpret_cast<const uint32_t*>(xh16 + o + 8*CIP + 8); \
    B0L[0] = *reinterpret_cast<const uint32_t*>(xl16 + o); \
    B0L[1] = *reinterpret_cast<const uint32_t*>(xl16 + o + 8); \
    B1L[0] = *reinterpret_cast<const uint32_t*>(xl16 + o + 8*CIP); \
    B1L[1] = *reinterpret_cast<const uint32_t*>(xl16 + o + 8*CIP + 8); \
} while (0)

#define MMA6(r, b) do { \
    mma_bf16(acc[r][0][0], aH[b][0], B0H); mma_bf16(acc[r][1][0], aH[b][1], B0H); \
    mma_bf16(acc[r][0][1], aH[b][0], B1H); mma_bf16(acc[r][1][1], aH[b][1], B1H); \
    mma_bf16(acc[r][0][0], aL[b][0], B0H); mma_bf16(acc[r][1][0], aL[b][1], B0H); \
    mma_bf16(acc[r][0][1], aL[b][0], B1H); mma_bf16(acc[r][1][1], aL[b][1], B1H); \
    mma_bf16(acc[r][0][0], aH[b][0], B0L); mma_bf16(acc[r][1][0], aH[b][1], B0L); \
    mma_bf16(acc[r][0][1], aH[b][0], B1L); mma_bf16(acc[r][1][1], aH[b][1], B1L); \
} while (0)

    #pragma unroll 1
    for (int t = 0; t < pairs; t++) {
        const int y = row0 + 2*t;
        int s_[4];
        #pragma unroll
        for (int dd = 0; dd < 4; dd++) s_[dd] = (y - 1 + dd + 6) % 6;

        float acc[2][2][2][4];
        #pragma unroll
        for (int r = 0; r < 2; r++)
            #pragma unroll
            for (int mi = 0; mi < 2; mi++)
                #pragma unroll
                for (int j = 0; j < 2; j++)
                    #pragma unroll
                    for (int q = 0; q < 4; q++) acc[r][mi][j][q] = 0.f;

        #pragma unroll 1
        for (int kwh = 0; kwh < 6; kwh++) {
            const int kw   = kwh >> 1;
            const int half = kwh & 1;
            const int hoff = half * 16;
            uint32_t aH[2][2][4], aL[2][2][4];
            uint32_t B0H[2], B1H[2], B0L[2], B1L[2];

            ALOAD(0, 0);                 // buf0 = kh0
            BLOAD(0);                    // d=-1: row0/kh0
            MMA6(0, 0);
            ALOAD(1, 1);                 // buf1 = kh1
            BLOAD(1);                    // d=0: row1/kh0, row0/kh1
            MMA6(1, 0);
            MMA6(0, 1);
            ALOAD(0, 2);                 // buf0 = kh2
            BLOAD(2);                    // d=1: row1/kh1, row0/kh2
            MMA6(1, 1);
            MMA6(0, 0);
            BLOAD(3);                    // d=2: row1/kh2
            MMA6(1, 0);
        }

        // ---- epilogue: 2 rows, bias + coalesced float2 stores ----
        #pragma unroll
        for (int r = 0; r < 2; r++) {
            const int yy = y + r;
            const int pxb = x0 + w*16 + laneq2;
            #pragma unroll
            for (int mi = 0; mi < 2; mi++) {
                const float bA = mi ? bias2 : bias0;
                const float bB = mi ? bias3 : bias1;
                const int coA = mi*16 + lanehi;
                float* o0 = out + (((size_t)n*COUT + coA)*HW + yy)*HW + pxb;
                #pragma unroll
                for (int j = 0; j < 2; j++) {
                    *reinterpret_cast<float2*>(o0 + 8*j) =
                        make_float2(acc[r][mi][j][0] + bA, acc[r][mi][j][1] + bA);
                    *reinterpret_cast<float2*>(o0 + 8*j + (size_t)8*HW*HW) =
                        make_float2(acc[r][mi][j][2] + bB, acc[r][mi][j][3] + bB);
                }
            }
        }

        if (t + 1 < pairs) {
            stage_row(xn, xh32, xl32, y + 3, x0, tid);
            stage_row(xn, xh32, xl32, y + 4, x0, tid);
        }
        __syncthreads();
    }
#undef ALOAD
#undef BLOAD
#undef MMA6
}

// ---------------------------------------------------------------------------
extern "C" void kernel_launch(void* const* d_in, const int* in_sizes, int n_in,
                              void* d_out, int out_size)
{
    const float* x      = (const float*)d_in[0];
    const float* y      = (const float*)d_in[1];
    const float* weight = (const float*)d_in[2];
    const float* fc_w1  = (const float*)d_in[3];
    const float* fc_b1  = (const float*)d_in[4];
    const float* fc_a   = (const float*)d_in[5];
    const float* fc_w2  = (const float*)d_in[6];
    const float* fc_b2  = (const float*)d_in[7];
    const float* b_w1   = (const float*)d_in[8];
    const float* b_b1   = (const float*)d_in[9];
    const float* b_a    = (const float*)d_in[10];
    const float* b_w2   = (const float*)d_in[11];
    const float* b_b2   = (const float*)d_in[12];
    float* out = (float*)d_out;

    cudaFuncSetAttribute(conv_mma,
                         cudaFuncAttributeMaxDynamicSharedMemorySize,
                         CONV_SMEM);

    mlp_fused<<<37, 256>>>(y, weight, fc_w1, fc_b1, fc_a, fc_w2, fc_b2,
                           b_w1, b_b1, b_a, b_w2, b_b2);
    conv_mma<<<dim3(74, BN), 384, CONV_SMEM>>>(x, out);
}

// round 7
// speedup vs baseline: 1.4193x; 1.4193x over previous
#include <cuda_runtime.h>
#include <cuda_bf16.h>
#include <math.h>
#include <stdint.h>

#define BN   8
#define CIN  32
#define COUT 32
#define HW   384
#define AUX  128
#define HID  256
#define MODOUT (COUT*CIN*9)   // 9216
#define KDIM 288              // k = tap*32 + ci
#define WST  296              // padded W row stride (conflict-free ldmatrix)

// Scratch (allocation-free rule: __device__ globals)
__device__ float g_bias[BN * COUT];
__device__ __nv_bfloat16 g_wh[BN * COUT * KDIM];  // [n][co][tap*32+ci] hi
__device__ __nv_bfloat16 g_wl[BN * COUT * KDIM];  // lo

// ---------------------------------------------------------------------------
// warp-MMA helpers (sm_80-class, valid on compute_103 without 'a')
// ---------------------------------------------------------------------------
__device__ __forceinline__ uint32_t smem_u32(const void* p) {
    uint32_t a;
    asm("{ .reg .u64 t; cvta.to.shared.u64 t, %1; cvt.u32.u64 %0, t; }"
        : "=r"(a) : "l"(p));
    return a;
}
__device__ __forceinline__ void ldm4(uint32_t r[4], uint32_t addr) {
    asm volatile("ldmatrix.sync.aligned.m8n8.x4.shared.b16 {%0,%1,%2,%3}, [%4];"
        : "=r"(r[0]), "=r"(r[1]), "=r"(r[2]), "=r"(r[3]) : "r"(addr));
}
__device__ __forceinline__ void mma_bf16(float d[4], const uint32_t a[4],
                                         const uint32_t b[2]) {
    asm volatile("mma.sync.aligned.m16n8k16.row.col.f32.bf16.bf16.f32 "
        "{%0,%1,%2,%3}, {%4,%5,%6,%7}, {%8,%9}, {%0,%1,%2,%3};"
        : "+f"(d[0]), "+f"(d[1]), "+f"(d[2]), "+f"(d[3])
        : "r"(a[0]), "r"(a[1]), "r"(a[2]), "r"(a[3]), "r"(b[0]), "r"(b[1]));
}
// pack two fp32 -> bf16x2 (lo = a, hi = b)
__device__ __forceinline__ uint32_t bf2pack(float a, float b) {
    uint32_t r;
    asm("cvt.rn.satfinite.bf16x2.f32 %0, %1, %2;" : "=r"(r) : "f"(b), "f"(a));
    return r;
}

// ---------------------------------------------------------------------------
// Fused MLP kernel (round-5 structure: grid 289, measured ~31us).
// ---------------------------------------------------------------------------
__global__ void mlp_fused(const float* __restrict__ y,
                          const float* __restrict__ weight,
                          const float* __restrict__ fc_w1, const float* __restrict__ fc_b1,
                          const float* __restrict__ fc_a_p,
                          const float* __restrict__ fc_w2, const float* __restrict__ fc_b2,
                          const float* __restrict__ b_w1,  const float* __restrict__ b_b1,
                          const float* __restrict__ b_a_p,
                          const float* __restrict__ b_w2,  const float* __restrict__ b_b2)
{
    __shared__ float y_s[BN * AUX];
    __shared__ float h_s[BN * HID];
    const int t = threadIdx.x;

    if (blockIdx.x < 288) {
        const int n  = blockIdx.x / 36;
        const int jb = (blockIdx.x % 36) * 256;

        if (t < AUX) y_s[t] = y[n*AUX + t];
        __syncthreads();

        {
            const float a = *fc_a_p;
            float acc[8] = {0,0,0,0,0,0,0,0};
            #pragma unroll
            for (int i = 0; i < AUX; i += 8) {
                #pragma unroll
                for (int q = 0; q < 8; q++)
                    acc[q] = fmaf(y_s[i+q], fc_w1[(i+q)*HID + t], acc[q]);
            }
            const float h = ((acc[0]+acc[1])+(acc[2]+acc[3]))
                          + ((acc[4]+acc[5])+(acc[6]+acc[7])) + fc_b1[t];
            h_s[t] = (h >= 0.f) ? h : a*h;
        }
        __syncthreads();

        const int j = jb + t;           // j = co*288 + ci*9 + tap
        float m0 = 0.f, m1 = 0.f, m2 = 0.f, m3 = 0.f;
        #pragma unroll 4
        for (int hh = 0; hh < HID; hh += 4) {
            m0 = fmaf(h_s[hh+0], fc_w2[(hh+0)*MODOUT + j], m0);
            m1 = fmaf(h_s[hh+1], fc_w2[(hh+1)*MODOUT + j], m1);
            m2 = fmaf(h_s[hh+2], fc_w2[(hh+2)*MODOUT + j], m2);
            m3 = fmaf(h_s[hh+3], fc_w2[(hh+3)*MODOUT + j], m3);
        }
        const float mm = (m0 + m1) + (m2 + m3) + fc_b2[j];
        const float sg = 1.f / (1.f + expf(-mm));
        const float wm = sg * weight[j];
        const int co  = j / 288;
        const int r   = j - co*288;
        const int ci  = r / 9;
        const int tap = r - ci*9;
        __nv_bfloat16 hi = __float2bfloat16(wm);
        __nv_bfloat16 lo = __float2bfloat16(wm - __bfloat162float(hi));
        const int o = (n*COUT + co)*KDIM + tap*32 + ci;
        g_wh[o] = hi;
        g_wl[o] = lo;
    } else {
        #pragma unroll
        for (int i = t; i < BN*AUX; i += 256) y_s[i] = y[i];
        __syncthreads();

        const float a = *b_a_p;
        #pragma unroll 1
        for (int n = 0; n < BN; n++) {
            float acc[4] = {0,0,0,0};
            #pragma unroll
            for (int i = 0; i < AUX; i += 4) {
                #pragma unroll
                for (int q = 0; q < 4; q++)
                    acc[q] = fmaf(y_s[n*AUX + i+q], b_w1[(i+q)*HID + t], acc[q]);
            }
            const float h = (acc[0]+acc[1]) + (acc[2]+acc[3]) + b_b1[t];
            h_s[n*HID + t] = (h >= 0.f) ? h : a*h;
        }
        __syncthreads();

        const int n  = t >> 5;
        const int co = t & 31;
        const float* hb = h_s + n*HID;
        float m0 = 0.f, m1 = 0.f, m2 = 0.f, m3 = 0.f;
        #pragma unroll 4
        for (int hh = 0; hh < HID; hh += 4) {
            m0 = fmaf(hb[hh+0], b_w2[(hh+0)*COUT + co], m0);
            m1 = fmaf(hb[hh+1], b_w2[(hh+1)*COUT + co], m1);
            m2 = fmaf(hb[hh+2], b_w2[(hh+2)*COUT + co], m2);
            m3 = fmaf(hb[hh+3], b_w2[(hh+3)*COUT + co], m3);
        }
        g_bias[n*COUT + co] = (m0 + m1) + (m2 + m3) + b_b2[co];
    }
}

// ---------------------------------------------------------------------------
// Conv: mma.sync bf16, 3-pass hi/lo, 2-row blocking, 2 CTAs/SM.
// CTA: 256 threads (8 warps), 128-px tile, strip of 16 rows (8 pairs).
// Slab: 4-slot rolling [slot][col(130)][ci pad 36]; smem total 110.3KB.
// Inner loop software-pipelined: B loads issued 12-24 MMAs ahead.
// ---------------------------------------------------------------------------
#define RC       130
#define CIP      36
#define NSLOT    4
#define SLAB_B   (NSLOT*RC*CIP*2)          // 37440 per array
#define W_BYTES  (COUT*WST*2)              // 18944
#define OFF_WH   0
#define OFF_WL   (W_BYTES)                 // 18944
#define OFF_XH   (2*W_BYTES)               // 37888
#define OFF_XL   (OFF_XH + SLAB_B)         // 75328
#define CONV_SMEM (OFF_XL + SLAB_B)        // 112768 -> 2 CTAs/SM

__device__ __forceinline__ void stage_row(const float* __restrict__ xn,
                                          uint32_t* __restrict__ xh32,
                                          uint32_t* __restrict__ xl32,
                                          int gy, int x0, int tid)
{
    const int slot = (gy + NSLOT) & (NSLOT - 1);
    const bool yok = (unsigned)gy < (unsigned)HW;
    for (int i = tid; i < 16*RC; i += 256) {      // ci-pair x col
        const int cp  = i / RC;
        const int col = i - cp*RC;
        const int gx  = x0 - 1 + col;
        float f0 = 0.f, f1 = 0.f;
        if (yok && (unsigned)gx < (unsigned)HW) {
            const float* p = xn + ((2*cp)*HW + gy)*HW + gx;
            f0 = p[0];
            f1 = p[HW*HW];
        }
        const uint32_t h = bf2pack(f0, f1);
        const float f0h = __uint_as_float(h << 16);
        const float f1h = __uint_as_float(h & 0xFFFF0000u);
        const uint32_t l = bf2pack(f0 - f0h, f1 - f1h);
        const int o = (slot*RC + col)*(CIP/2) + cp;
        xh32[o] = h;
        xl32[o] = l;
    }
}

__global__ void __launch_bounds__(256, 2)
conv_mma(const float* __restrict__ x, float* __restrict__ out)
{
    extern __shared__ char smem[];
    uint16_t* xh16 = reinterpret_cast<uint16_t*>(smem + OFF_XH);
    uint16_t* xl16 = reinterpret_cast<uint16_t*>(smem + OFF_XL);
    uint32_t* xh32 = reinterpret_cast<uint32_t*>(smem + OFF_XH);
    uint32_t* xl32 = reinterpret_cast<uint32_t*>(smem + OFF_XL);

    const int tid  = threadIdx.x;
    const int lane = tid & 31;
    const int w    = tid >> 5;
    const int n    = blockIdx.y;
    const int xt   = blockIdx.x % 3;
    const int st   = blockIdx.x / 3;            // 0..23
    const int x0   = xt * 128;
    const int row0 = st * 16;

    // ---- per-sample weights -> padded smem (vectorized u32) ----
    {
        const uint32_t* gh = reinterpret_cast<const uint32_t*>(g_wh + (size_t)n*MODOUT);
        const uint32_t* gl = reinterpret_cast<const uint32_t*>(g_wl + (size_t)n*MODOUT);
        uint32_t* whs = reinterpret_cast<uint32_t*>(smem + OFF_WH);
        uint32_t* wls = reinterpret_cast<uint32_t*>(smem + OFF_WL);
        for (int i = tid; i < COUT*(KDIM/2); i += 256) {
            const int co = i / 144, k2 = i - co*144;
            whs[co*(WST/2) + k2] = gh[i];
            wls[co*(WST/2) + k2] = gl[i];
        }
    }
    const int lanehi = lane >> 2;
    const int laneq2 = (lane & 3) * 2;
    const float bias0 = g_bias[n*COUT + lanehi];
    const float bias1 = g_bias[n*COUT + lanehi + 8];
    const float bias2 = g_bias[n*COUT + lanehi + 16];
    const float bias3 = g_bias[n*COUT + lanehi + 24];

    const float* xn = x + (size_t)n * CIN * HW * HW;
    stage_row(xn, xh32, xl32, row0 - 1, x0, tid);
    stage_row(xn, xh32, xl32, row0,     x0, tid);
    stage_row(xn, xh32, xl32, row0 + 1, x0, tid);
    stage_row(xn, xh32, xl32, row0 + 2, x0, tid);
    __syncthreads();

    const uint32_t sb   = smem_u32(smem);
    const uint32_t aoff = (uint32_t)(((lane & 15)*WST + (lane >> 4)*8) * 2);
    const uint32_t whb  = sb + OFF_WH + aoff;
    const uint32_t wlb  = sb + OFF_WL + aoff;
    const int colb = w*16 + lanehi;

#define ALOAD(b, kh) do { \
    const uint32_t c32 = (uint32_t)(((kh)*3 + kw)*2 + half) * 32u; \
    ldm4(aH[b][0], whb + c32); ldm4(aH[b][1], whb + c32 + 16*WST*2); \
    ldm4(aL[b][0], wlb + c32); ldm4(aL[b][1], wlb + c32 + 16*WST*2); \
} while (0)

#define BLOAD(b, dd) do { \
    const int o = (s_[dd]*RC + colb + kw)*CIP + hoff + laneq2; \
    bH[b][0][0] = *reinterpret_cast<const uint32_t*>(xh16 + o); \
    bH[b][0][1] = *reinterpret_cast<const uint32_t*>(xh16 + o + 8); \
    bH[b][1][0] = *reinterpret_cast<const uint32_t*>(xh16 + o + 8*CIP); \
    bH[b][1][1] = *reinterpret_cast<const uint32_t*>(xh16 + o + 8*CIP + 8); \
    bL[b][0][0] = *reinterpret_cast<const uint32_t*>(xl16 + o); \
    bL[b][0][1] = *reinterpret_cast<const uint32_t*>(xl16 + o + 8); \
    bL[b][1][0] = *reinterpret_cast<const uint32_t*>(xl16 + o + 8*CIP); \
    bL[b][1][1] = *reinterpret_cast<const uint32_t*>(xl16 + o + 8*CIP + 8); \
} while (0)

#define MMA6(r, ab, bb) do { \
    mma_bf16(acc[r][0][0], aH[ab][0], bH[bb][0]); mma_bf16(acc[r][1][0], aH[ab][1], bH[bb][0]); \
    mma_bf16(acc[r][0][1], aH[ab][0], bH[bb][1]); mma_bf16(acc[r][1][1], aH[ab][1], bH[bb][1]); \
    mma_bf16(acc[r][0][0], aL[ab][0], bH[bb][0]); mma_bf16(acc[r][1][0], aL[ab][1], bH[bb][0]); \
    mma_bf16(acc[r][0][1], aL[ab][0], bH[bb][1]); mma_bf16(acc[r][1][1], aL[ab][1], bH[bb][1]); \
    mma_bf16(acc[r][0][0], aH[ab][0], bL[bb][0]); mma_bf16(acc[r][1][0], aH[ab][1], bL[bb][0]); \
    mma_bf16(acc[r][0][1], aH[ab][0], bL[bb][1]); mma_bf16(acc[r][1][1], aH[ab][1], bL[bb][1]); \
} while (0)

    #pragma unroll 1
    for (int t = 0; t < 8; t++) {
        const int y = row0 + 2*t;
        int s_[4];
        #pragma unroll
        for (int dd = 0; dd < 4; dd++) s_[dd] = (y - 1 + dd) & (NSLOT - 1);

        float acc[2][2][2][4];
        #pragma unroll
        for (int r = 0; r < 2; r++)
            #pragma unroll
            for (int mi = 0; mi < 2; mi++)
                #pragma unroll
                for (int j = 0; j < 2; j++)
                    #pragma unroll
                    for (int q = 0; q < 4; q++) acc[r][mi][j][q] = 0.f;

        #pragma unroll 1
        for (int kwh = 0; kwh < 6; kwh++) {
            const int kw   = kwh >> 1;
            const int half = kwh & 1;
            const int hoff = half * 16;
            uint32_t aH[2][2][4], aL[2][2][4];
            uint32_t bH[2][2][2], bL[2][2][2];

            // software pipeline: every BLOAD has >=12 MMAs before first use
            ALOAD(0, 0);                 // A: kh0
            BLOAD(0, 0);                 // B: d=-1
            ALOAD(1, 1);                 // A: kh1
            BLOAD(1, 1);                 // B: d=0
            MMA6(0, 0, 0);               // row0/kh0 @ d=-1
            BLOAD(0, 2);                 // B: d=1 (reuse buf0)
            MMA6(1, 0, 1);               // row1/kh0 @ d=0
            MMA6(0, 1, 1);               // row0/kh1 @ d=0
            ALOAD(0, 2);                 // A: kh2 (reuse abuf0)
            MMA6(1, 1, 0);               // row1/kh1 @ d=1
            BLOAD(1, 3);                 // B: d=2 (reuse buf1)
            MMA6(0, 0, 0);               // row0/kh2 @ d=1
            MMA6(1, 0, 1);               // row1/kh2 @ d=2
        }

        // ---- epilogue: 2 rows, bias + coalesced float2 stores ----
        #pragma unroll
        for (int r = 0; r < 2; r++) {
            const int yy = y + r;
            const int pxb = x0 + w*16 + laneq2;
            #pragma unroll
            for (int mi = 0; mi < 2; mi++) {
                const float bA = mi ? bias2 : bias0;
                const float bB = mi ? bias3 : bias1;
                const int coA = mi*16 + lanehi;
                float* o0 = out + (((size_t)n*COUT + coA)*HW + yy)*HW + pxb;
                #pragma unroll
                for (int j = 0; j < 2; j++) {
                    *reinterpret_cast<float2*>(o0 + 8*j) =
                        make_float2(acc[r][mi][j][0] + bA, acc[r][mi][j][1] + bA);
                    *reinterpret_cast<float2*>(o0 + 8*j + (size_t)8*HW*HW) =
                        make_float2(acc[r][mi][j][2] + bB, acc[r][mi][j][3] + bB);
                }
            }
        }

        if (t < 7) {
            __syncthreads();
            stage_row(xn, xh32, xl32, y + 3, x0, tid);
            stage_row(xn, xh32, xl32, y + 4, x0, tid);
            __syncthreads();
        }
    }
#undef ALOAD
#undef BLOAD
#undef MMA6
}

// ---------------------------------------------------------------------------
extern "C" void kernel_launch(void* const* d_in, const int* in_sizes, int n_in,
                              void* d_out, int out_size)
{
    const float* x      = (const float*)d_in[0];
    const float* y      = (const float*)d_in[1];
    const float* weight = (const float*)d_in[2];
    const float* fc_w1  = (const float*)d_in[3];
    const float* fc_b1  = (const float*)d_in[4];
    const float* fc_a   = (const float*)d_in[5];
    const float* fc_w2  = (const float*)d_in[6];
    const float* fc_b2  = (const float*)d_in[7];
    const float* b_w1   = (const float*)d_in[8];
    const float* b_b1   = (const float*)d_in[9];
    const float* b_a    = (const float*)d_in[10];
    const float* b_w2   = (const float*)d_in[11];
    const float* b_b2   = (const float*)d_in[12];
    float* out = (float*)d_out;

    cudaFuncSetAttribute(conv_mma,
                         cudaFuncAttributeMaxDynamicSharedMemorySize,
                         CONV_SMEM);

    mlp_fused<<<289, 256>>>(y, weight, fc_w1, fc_b1, fc_a, fc_w2, fc_b2,
                            b_w1, b_b1, b_a, b_w2, b_b2);
    conv_mma<<<dim3(72, BN), 256, CONV_SMEM>>>(x, out);
}

// round 8
// speedup vs baseline: 2.1330x; 1.5028x over previous
#include <cuda_runtime.h>
#include <cuda_fp16.h>
#include <math.h>
#include <stdint.h>

#define BN   8
#define CIN  32
#define COUT 32
#define HW   384
#define AUX  128
#define HID  256
#define MODOUT (COUT*CIN*9)   // 9216
#define KDIM 288              // k = tap*32 + ci
#define WST  296              // padded W row stride (conflict-free ldmatrix)

// Scratch (allocation-free rule: __device__ globals)
__device__ float g_bias[BN * COUT];
__device__ __half g_w[BN * COUT * KDIM];   // [n][co][tap*32+ci] fp16

// ---------------------------------------------------------------------------
// warp-MMA helpers (sm_80-class, valid on compute_103 without 'a')
// ---------------------------------------------------------------------------
__device__ __forceinline__ uint32_t smem_u32(const void* p) {
    uint32_t a;
    asm("{ .reg .u64 t; cvta.to.shared.u64 t, %1; cvt.u32.u64 %0, t; }"
        : "=r"(a) : "l"(p));
    return a;
}
__device__ __forceinline__ void ldm4(uint32_t r[4], uint32_t addr) {
    asm volatile("ldmatrix.sync.aligned.m8n8.x4.shared.b16 {%0,%1,%2,%3}, [%4];"
        : "=r"(r[0]), "=r"(r[1]), "=r"(r[2]), "=r"(r[3]) : "r"(addr));
}
__device__ __forceinline__ void mma_f16(float d[4], const uint32_t a[4],
                                        const uint32_t b[2]) {
    asm volatile("mma.sync.aligned.m16n8k16.row.col.f32.f16.f16.f32 "
        "{%0,%1,%2,%3}, {%4,%5,%6,%7}, {%8,%9}, {%0,%1,%2,%3};"
        : "+f"(d[0]), "+f"(d[1]), "+f"(d[2]), "+f"(d[3])
        : "r"(a[0]), "r"(a[1]), "r"(a[2]), "r"(a[3]), "r"(b[0]), "r"(b[1]));
}

// ---------------------------------------------------------------------------
// Fused MLP kernel: grid 289.
// ---------------------------------------------------------------------------
__global__ void mlp_fused(const float* __restrict__ y,
                          const float* __restrict__ weight,
                          const float* __restrict__ fc_w1, const float* __restrict__ fc_b1,
                          const float* __restrict__ fc_a_p,
                          const float* __restrict__ fc_w2, const float* __restrict__ fc_b2,
                          const float* __restrict__ b_w1,  const float* __restrict__ b_b1,
                          const float* __restrict__ b_a_p,
                          const float* __restrict__ b_w2,  const float* __restrict__ b_b2)
{
    __shared__ float y_s[BN * AUX];
    __shared__ float h_s[BN * HID];
    const int t = threadIdx.x;

    if (blockIdx.x < 288) {
        const int n  = blockIdx.x / 36;
        const int jb = (blockIdx.x % 36) * 256;

        if (t < AUX) y_s[t] = y[n*AUX + t];
        __syncthreads();

        {
            const float a = *fc_a_p;
            float acc[8] = {0,0,0,0,0,0,0,0};
            #pragma unroll
            for (int i = 0; i < AUX; i += 8) {
                #pragma unroll
                for (int q = 0; q < 8; q++)
                    acc[q] = fmaf(y_s[i+q], fc_w1[(i+q)*HID + t], acc[q]);
            }
            const float h = ((acc[0]+acc[1])+(acc[2]+acc[3]))
                          + ((acc[4]+acc[5])+(acc[6]+acc[7])) + fc_b1[t];
            h_s[t] = (h >= 0.f) ? h : a*h;
        }
        __syncthreads();

        const int j = jb + t;           // j = co*288 + ci*9 + tap
        float m[8] = {0,0,0,0,0,0,0,0};
        #pragma unroll 4
        for (int hh = 0; hh < HID; hh += 8) {
            #pragma unroll
            for (int q = 0; q < 8; q++)
                m[q] = fmaf(h_s[hh+q], fc_w2[(hh+q)*MODOUT + j], m[q]);
        }
        const float mm = ((m[0]+m[1])+(m[2]+m[3]))
                       + ((m[4]+m[5])+(m[6]+m[7])) + fc_b2[j];
        const float sg = 1.f / (1.f + expf(-mm));
        const float wm = sg * weight[j];
        const int co  = j / 288;
        const int r   = j - co*288;
        const int ci  = r / 9;
        const int tap = r - ci*9;
        g_w[(n*COUT + co)*KDIM + tap*32 + ci] = __float2half_rn(wm);
    } else {
        #pragma unroll
        for (int i = t; i < BN*AUX; i += 256) y_s[i] = y[i];
        __syncthreads();

        const float a = *b_a_p;
        #pragma unroll 1
        for (int n = 0; n < BN; n++) {
            float acc[4] = {0,0,0,0};
            #pragma unroll
            for (int i = 0; i < AUX; i += 4) {
                #pragma unroll
                for (int q = 0; q < 4; q++)
                    acc[q] = fmaf(y_s[n*AUX + i+q], b_w1[(i+q)*HID + t], acc[q]);
            }
            const float h = (acc[0]+acc[1]) + (acc[2]+acc[3]) + b_b1[t];
            h_s[n*HID + t] = (h >= 0.f) ? h : a*h;
        }
        __syncthreads();

        const int n  = t >> 5;
        const int co = t & 31;
        const float* hb = h_s + n*HID;
        float m0 = 0.f, m1 = 0.f, m2 = 0.f, m3 = 0.f;
        #pragma unroll 4
        for (int hh = 0; hh < HID; hh += 4) {
            m0 = fmaf(hb[hh+0], b_w2[(hh+0)*COUT + co], m0);
            m1 = fmaf(hb[hh+1], b_w2[(hh+1)*COUT + co], m1);
            m2 = fmaf(hb[hh+2], b_w2[(hh+2)*COUT + co], m2);
            m3 = fmaf(hb[hh+3], b_w2[(hh+3)*COUT + co], m3);
        }
        g_bias[n*COUT + co] = (m0 + m1) + (m2 + m3) + b_b2[co];
    }
}

// ---------------------------------------------------------------------------
// Conv: mma.sync fp16 single-pass implicit GEMM, 2-row blocking, 3 CTAs/SM.
// CTA: 256 threads (8 warps), 128-px tile, variable strip (12 or 10 rows).
// Slab: 4-slot rolling [slot][col(130)][ci pad 40] fp16; conflict-free.
// Grid: 37 strips x 3 xtiles x 8 samples = 888 = 2.0 waves @ 3 CTAs/SM.
// ---------------------------------------------------------------------------
#define RC       130
#define CIP      40
#define NSLOT    4
#define SLAB_B   (NSLOT*RC*CIP*2)          // 41600
#define W_BYTES  (COUT*WST*2)              // 18944
#define OFF_W    0
#define OFF_X    (W_BYTES)                 // 18944
#define CONV_SMEM (OFF_X + SLAB_B)         // 60544 -> 3 CTAs/SM

__device__ __forceinline__ void stage_row(const float* __restrict__ xn,
                                          uint32_t* __restrict__ xs32,
                                          int gy, int x0, int tid)
{
    const int slot = (gy + NSLOT) & (NSLOT - 1);
    const bool yok = (unsigned)gy < (unsigned)HW;
    for (int i = tid; i < 16*RC; i += 256) {      // ci-pair x col
        const int cp  = i / RC;
        const int col = i - cp*RC;
        const int gx  = x0 - 1 + col;
        float f0 = 0.f, f1 = 0.f;
        if (yok && (unsigned)gx < (unsigned)HW) {
            const float* p = xn + ((2*cp)*HW + gy)*HW + gx;
            f0 = p[0];
            f1 = p[HW*HW];
        }
        const __half2 h2 = __floats2half2_rn(f0, f1);   // lo=f0, hi=f1
        xs32[(slot*RC + col)*(CIP/2) + cp] = *reinterpret_cast<const uint32_t*>(&h2);
    }
}

__global__ void __launch_bounds__(256, 3)
conv_mma(const float* __restrict__ x, float* __restrict__ out)
{
    extern __shared__ char smem[];
    uint16_t* xs16 = reinterpret_cast<uint16_t*>(smem + OFF_X);
    uint32_t* xs32 = reinterpret_cast<uint32_t*>(smem + OFF_X);

    const int tid  = threadIdx.x;
    const int lane = tid & 31;
    const int w    = tid >> 5;
    const int n    = blockIdx.y;
    const int xt   = blockIdx.x % 3;
    const int st   = blockIdx.x / 3;            // 0..36
    const int x0   = xt * 128;
    const int row0  = (st < 7) ? st*12 : 84 + (st-7)*10;
    const int pairs = (st < 7) ? 6 : 5;

    // ---- per-sample weights -> padded smem rows (vectorized u32) ----
    {
        const uint32_t* gw = reinterpret_cast<const uint32_t*>(g_w + (size_t)n*MODOUT);
        uint32_t* ws = reinterpret_cast<uint32_t*>(smem + OFF_W);
        for (int i = tid; i < COUT*(KDIM/2); i += 256) {
            const int co = i / 144, k2 = i - co*144;
            ws[co*(WST/2) + k2] = gw[i];
        }
    }
    const int lanehi = lane >> 2;
    const int laneq2 = (lane & 3) * 2;
    const float bias0 = g_bias[n*COUT + lanehi];
    const float bias1 = g_bias[n*COUT + lanehi + 8];
    const float bias2 = g_bias[n*COUT + lanehi + 16];
    const float bias3 = g_bias[n*COUT + lanehi + 24];

    const float* xn = x + (size_t)n * CIN * HW * HW;
    stage_row(xn, xs32, row0 - 1, x0, tid);
    stage_row(xn, xs32, row0,     x0, tid);
    stage_row(xn, xs32, row0 + 1, x0, tid);
    stage_row(xn, xs32, row0 + 2, x0, tid);
    __syncthreads();

    const uint32_t sb   = smem_u32(smem);
    const uint32_t aoff = (uint32_t)(((lane & 15)*WST + (lane >> 4)*8) * 2);
    const uint32_t wbase = sb + OFF_W + aoff;
    const int colb = w*16 + lanehi;

#define ALOAD(b, kh) do { \
    const uint32_t c32 = (uint32_t)(((kh)*3 + kw)*2 + half) * 32u; \
    ldm4(aA[b][0], wbase + c32); ldm4(aA[b][1], wbase + c32 + 16*WST*2); \
} while (0)

#define BLOAD(b, dd) do { \
    const int o = (s_[dd]*RC + colb + kw)*CIP + hoff + laneq2; \
    bB[b][0][0] = *reinterpret_cast<const uint32_t*>(xs16 + o); \
    bB[b][0][1] = *reinterpret_cast<const uint32_t*>(xs16 + o + 8); \
    bB[b][1][0] = *reinterpret_cast<const uint32_t*>(xs16 + o + 8*CIP); \
    bB[b][1][1] = *reinterpret_cast<const uint32_t*>(xs16 + o + 8*CIP + 8); \
} while (0)

#define MMA4(r, ab, bb) do { \
    mma_f16(acc[r][0][0], aA[ab][0], bB[bb][0]); \
    mma_f16(acc[r][1][0], aA[ab][1], bB[bb][0]); \
    mma_f16(acc[r][0][1], aA[ab][0], bB[bb][1]); \
    mma_f16(acc[r][1][1], aA[ab][1], bB[bb][1]); \
} while (0)

    #pragma unroll 1
    for (int t = 0; t < pairs; t++) {
        const int y = row0 + 2*t;
        int s_[4];
        #pragma unroll
        for (int dd = 0; dd < 4; dd++) s_[dd] = (y - 1 + dd) & (NSLOT - 1);

        float acc[2][2][2][4];
        #pragma unroll
        for (int r = 0; r < 2; r++)
            #pragma unroll
            for (int mi = 0; mi < 2; mi++)
                #pragma unroll
                for (int j = 0; j < 2; j++)
                    #pragma unroll
                    for (int q = 0; q < 4; q++) acc[r][mi][j][q] = 0.f;

        #pragma unroll 1
        for (int kwh = 0; kwh < 6; kwh++) {
            const int kw   = kwh >> 1;
            const int half = kwh & 1;
            const int hoff = half * 16;
            uint32_t aA[2][2][4];
            uint32_t bB[2][2][2];

            ALOAD(0, 0);                 // A: kh0
            BLOAD(0, 0);                 // B: d=-1
            ALOAD(1, 1);                 // A: kh1
            BLOAD(1, 1);                 // B: d=0
            MMA4(0, 0, 0);               // row0/kh0 @ d=-1
            BLOAD(0, 2);                 // B: d=1 (reuse buf0)
            MMA4(1, 0, 1);               // row1/kh0 @ d=0
            MMA4(0, 1, 1);               // row0/kh1 @ d=0
            ALOAD(0, 2);                 // A: kh2 (reuse abuf0)
            MMA4(1, 1, 0);               // row1/kh1 @ d=1
            BLOAD(1, 3);                 // B: d=2 (reuse buf1)
            MMA4(0, 0, 0);               // row0/kh2 @ d=1
            MMA4(1, 0, 1);               // row1/kh2 @ d=2
        }

        // ---- epilogue: 2 rows, bias + coalesced float2 stores ----
        #pragma unroll
        for (int r = 0; r < 2; r++) {
            const int yy = y + r;
            const int pxb = x0 + w*16 + laneq2;
            #pragma unroll
            for (int mi = 0; mi < 2; mi++) {
                const float bA = mi ? bias2 : bias0;
                const float bB2 = mi ? bias3 : bias1;
                const int coA = mi*16 + lanehi;
                float* o0 = out + (((size_t)n*COUT + coA)*HW + yy)*HW + pxb;
                #pragma unroll
                for (int j = 0; j < 2; j++) {
                    *reinterpret_cast<float2*>(o0 + 8*j) =
                        make_float2(acc[r][mi][j][0] + bA, acc[r][mi][j][1] + bA);
                    *reinterpret_cast<float2*>(o0 + 8*j + (size_t)8*HW*HW) =
                        make_float2(acc[r][mi][j][2] + bB2, acc[r][mi][j][3] + bB2);
                }
            }
        }

        if (t + 1 < pairs) {
            __syncthreads();
            stage_row(xn, xs32, y + 3, x0, tid);
            stage_row(xn, xs32, y + 4, x0, tid);
            __syncthreads();
        }
    }
#undef ALOAD
#undef BLOAD
#undef MMA4
}

// ---------------------------------------------------------------------------
extern "C" void kernel_launch(void* const* d_in, const int* in_sizes, int n_in,
                              void* d_out, int out_size)
{
    const float* x      = (const float*)d_in[0];
    const float* y      = (const float*)d_in[1];
    const float* weight = (const float*)d_in[2];
    const float* fc_w1  = (const float*)d_in[3];
    const float* fc_b1  = (const float*)d_in[4];
    const float* fc_a   = (const float*)d_in[5];
    const float* fc_w2  = (const float*)d_in[6];
    const float* fc_b2  = (const float*)d_in[7];
    const float* b_w1   = (const float*)d_in[8];
    const float* b_b1   = (const float*)d_in[9];
    const float* b_a    = (const float*)d_in[10];
    const float* b_w2   = (const float*)d_in[11];
    const float* b_b2   = (const float*)d_in[12];
    float* out = (float*)d_out;

    cudaFuncSetAttribute(conv_mma,
                         cudaFuncAttributeMaxDynamicSharedMemorySize,
                         CONV_SMEM);

    mlp_fused<<<289, 256>>>(y, weight, fc_w1, fc_b1, fc_a, fc_w2, fc_b2,
                            b_w1, b_b1, b_a, b_w2, b_b2);
    conv_mma<<<dim3(111, BN), 256, CONV_SMEM>>>(x, out);
}

// round 9
// speedup vs baseline: 2.6318x; 1.2339x over previous
#include <cuda_runtime.h>
#include <cuda_fp16.h>
#include <math.h>
#include <stdint.h>

#define BN   8
#define CIN  32
#define COUT 32
#define HW   384
#define AUX  128
#define HID  256
#define MODOUT (COUT*CIN*9)   // 9216
#define KDIM 288              // k = tap*32 + ci
#define WST  296              // padded W row stride (conflict-free ldmatrix)

// Scratch (allocation-free rule: __device__ globals)
__device__ float g_bias[BN * COUT];
__device__ __half g_w[BN * COUT * KDIM];   // [n][co][tap*32+ci] fp16

// ---------------------------------------------------------------------------
// warp-MMA helpers (sm_80-class, valid on compute_103 without 'a')
// ---------------------------------------------------------------------------
__device__ __forceinline__ uint32_t smem_u32(const void* p) {
    uint32_t a;
    asm("{ .reg .u64 t; cvta.to.shared.u64 t, %1; cvt.u32.u64 %0, t; }"
        : "=r"(a) : "l"(p));
    return a;
}
__device__ __forceinline__ void ldm4(uint32_t r[4], uint32_t addr) {
    asm volatile("ldmatrix.sync.aligned.m8n8.x4.shared.b16 {%0,%1,%2,%3}, [%4];"
        : "=r"(r[0]), "=r"(r[1]), "=r"(r[2]), "=r"(r[3]) : "r"(addr));
}
__device__ __forceinline__ void mma_f16(float d[4], const uint32_t a[4],
                                        const uint32_t b[2]) {
    asm volatile("mma.sync.aligned.m16n8k16.row.col.f32.f16.f16.f32 "
        "{%0,%1,%2,%3}, {%4,%5,%6,%7}, {%8,%9}, {%0,%1,%2,%3};"
        : "+f"(d[0]), "+f"(d[1]), "+f"(d[2]), "+f"(d[3])
        : "r"(a[0]), "r"(a[1]), "r"(a[2]), "r"(a[3]), "r"(b[0]), "r"(b[1]));
}

// ---------------------------------------------------------------------------
// MLP kernels.
// mlp_mod: grid 576 (8 n x 72 chunks of 128 j). Block 256 = 2 HID-halves.
// mlp_bias: handled by block 576 of the same launch.
// ---------------------------------------------------------------------------
__global__ void mlp_fused(const float* __restrict__ y,
                          const float* __restrict__ weight,
                          const float* __restrict__ fc_w1, const float* __restrict__ fc_b1,
                          const float* __restrict__ fc_a_p,
                          const float* __restrict__ fc_w2, const float* __restrict__ fc_b2,
                          const float* __restrict__ b_w1,  const float* __restrict__ b_b1,
                          const float* __restrict__ b_a_p,
                          const float* __restrict__ b_w2,  const float* __restrict__ b_b2)
{
    __shared__ float y_s[BN * AUX];
    __shared__ float h_s[BN * HID];
    __shared__ float part[256];
    const int t = threadIdx.x;

    if (blockIdx.x < 576) {
        const int n  = blockIdx.x / 72;
        const int jb = (blockIdx.x % 72) * 128;

        if (t < AUX) y_s[t] = y[n*AUX + t];
        __syncthreads();

        // hidden layer: thread t -> h[t] (all 256 threads)
        {
            const float a = *fc_a_p;
            float acc[8] = {0,0,0,0,0,0,0,0};
            #pragma unroll
            for (int i = 0; i < AUX; i += 8) {
                #pragma unroll
                for (int q = 0; q < 8; q++)
                    acc[q] = fmaf(y_s[i+q], fc_w1[(i+q)*HID + t], acc[q]);
            }
            const float h = ((acc[0]+acc[1])+(acc[2]+acc[3]))
                          + ((acc[4]+acc[5])+(acc[6]+acc[7])) + fc_b1[t];
            h_s[t] = (h >= 0.f) ? h : a*h;
        }
        __syncthreads();

        // output layer, HID split in two 128-wide halves
        const int tj = t & 127;
        const int g  = t >> 7;
        const int j  = jb + tj;          // j = co*288 + ci*9 + tap
        const int h0 = g * 128;
        float m[8] = {0,0,0,0,0,0,0,0};
        #pragma unroll 4
        for (int hh = 0; hh < 128; hh += 8) {
            #pragma unroll
            for (int q = 0; q < 8; q++)
                m[q] = fmaf(h_s[h0+hh+q], fc_w2[(h0+hh+q)*MODOUT + j], m[q]);
        }
        part[t] = ((m[0]+m[1])+(m[2]+m[3])) + ((m[4]+m[5])+(m[6]+m[7]));
        __syncthreads();

        if (t < 128) {
            const float mm = part[t] + part[t+128] + fc_b2[j];
            const float sg = 1.f / (1.f + expf(-mm));
            const float wm = sg * weight[j];
            const int co  = j / 288;
            const int r   = j - co*288;
            const int ci  = r / 9;
            const int tap = r - ci*9;
            g_w[(n*COUT + co)*KDIM + tap*32 + ci] = __float2half_rn(wm);
        }
    } else {
        // ---- bias branch ----
        #pragma unroll
        for (int i = t; i < BN*AUX; i += 256) y_s[i] = y[i];
        __syncthreads();

        const float a = *b_a_p;
        #pragma unroll 1
        for (int n = 0; n < BN; n++) {
            float acc[4] = {0,0,0,0};
            #pragma unroll
            for (int i = 0; i < AUX; i += 4) {
                #pragma unroll
                for (int q = 0; q < 4; q++)
                    acc[q] = fmaf(y_s[n*AUX + i+q], b_w1[(i+q)*HID + t], acc[q]);
            }
            const float h = (acc[0]+acc[1]) + (acc[2]+acc[3]) + b_b1[t];
            h_s[n*HID + t] = (h >= 0.f) ? h : a*h;
        }
        __syncthreads();

        const int n  = t >> 5;
        const int co = t & 31;
        const float* hb = h_s + n*HID;
        float m0 = 0.f, m1 = 0.f, m2 = 0.f, m3 = 0.f;
        #pragma unroll 4
        for (int hh = 0; hh < HID; hh += 4) {
            m0 = fmaf(hb[hh+0], b_w2[(hh+0)*COUT + co], m0);
            m1 = fmaf(hb[hh+1], b_w2[(hh+1)*COUT + co], m1);
            m2 = fmaf(hb[hh+2], b_w2[(hh+2)*COUT + co], m2);
            m3 = fmaf(hb[hh+3], b_w2[(hh+3)*COUT + co], m3);
        }
        g_bias[n*COUT + co] = (m0 + m1) + (m2 + m3) + b_b2[co];
    }
}

// ---------------------------------------------------------------------------
// Conv: mma.sync fp16 single-pass implicit GEMM, 2-row blocking, 3 CTAs/SM.
// Staging fully unrolled: all LDGs batched (MLP up to 36) before any STS.
// ---------------------------------------------------------------------------
#define RC       130
#define CIP      40
#define NSLOT    4
#define SLAB_B   (NSLOT*RC*CIP*2)          // 41600
#define W_BYTES  (COUT*WST*2)              // 18944
#define OFF_W    0
#define OFF_X    (W_BYTES)                 // 18944
#define CONV_SMEM (OFF_X + SLAB_B)         // 60544 -> 3 CTAs/SM
#define NSTG     9                         // ceil(16*RC/256)

__device__ __forceinline__ void stage_row(const float* __restrict__ xn,
                                          uint32_t* __restrict__ xs32,
                                          int gy, int x0, int tid)
{
    const int slot = (gy + NSLOT) & (NSLOT - 1);
    const bool yok = (unsigned)gy < (unsigned)HW;
    float v0[NSTG], v1[NSTG];
    #pragma unroll
    for (int it = 0; it < NSTG; it++) {
        const int i = tid + it*256;
        const int cp  = i / RC;
        const int col = i - cp*RC;
        const int gx  = x0 - 1 + col;
        float f0 = 0.f, f1 = 0.f;
        if (i < 16*RC && yok && (unsigned)gx < (unsigned)HW) {
            const float* p = xn + ((2*cp)*HW + gy)*HW + gx;
            f0 = p[0];
            f1 = p[HW*HW];
        }
        v0[it] = f0; v1[it] = f1;
    }
    #pragma unroll
    for (int it = 0; it < NSTG; it++) {
        const int i = tid + it*256;
        if (i < 16*RC) {
            const int cp  = i / RC;
            const int col = i - cp*RC;
            const __half2 h2 = __floats2half2_rn(v0[it], v1[it]);
            xs32[(slot*RC + col)*(CIP/2) + cp] = *reinterpret_cast<const uint32_t*>(&h2);
        }
    }
}

__global__ void __launch_bounds__(256, 3)
conv_mma(const float* __restrict__ x, float* __restrict__ out)
{
    extern __shared__ char smem[];
    uint16_t* xs16 = reinterpret_cast<uint16_t*>(smem + OFF_X);
    uint32_t* xs32 = reinterpret_cast<uint32_t*>(smem + OFF_X);

    const int tid  = threadIdx.x;
    const int lane = tid & 31;
    const int w    = tid >> 5;
    const int n    = blockIdx.y;
    const int xt   = blockIdx.x % 3;
    const int st   = blockIdx.x / 3;            // 0..36
    const int x0   = xt * 128;
    const int row0  = (st < 7) ? st*12 : 84 + (st-7)*10;
    const int pairs = (st < 7) ? 6 : 5;

    // ---- per-sample weights -> padded smem rows (vectorized u32) ----
    {
        const uint32_t* gw = reinterpret_cast<const uint32_t*>(g_w + (size_t)n*MODOUT);
        uint32_t* ws = reinterpret_cast<uint32_t*>(smem + OFF_W);
        for (int i = tid; i < COUT*(KDIM/2); i += 256) {
            const int co = i / 144, k2 = i - co*144;
            ws[co*(WST/2) + k2] = gw[i];
        }
    }
    const int lanehi = lane >> 2;
    const int laneq2 = (lane & 3) * 2;
    const float bias0 = g_bias[n*COUT + lanehi];
    const float bias1 = g_bias[n*COUT + lanehi + 8];
    const float bias2 = g_bias[n*COUT + lanehi + 16];
    const float bias3 = g_bias[n*COUT + lanehi + 24];

    const float* xn = x + (size_t)n * CIN * HW * HW;
    stage_row(xn, xs32, row0 - 1, x0, tid);
    stage_row(xn, xs32, row0,     x0, tid);
    stage_row(xn, xs32, row0 + 1, x0, tid);
    stage_row(xn, xs32, row0 + 2, x0, tid);
    __syncthreads();

    const uint32_t sb   = smem_u32(smem);
    const uint32_t aoff = (uint32_t)(((lane & 15)*WST + (lane >> 4)*8) * 2);
    const uint32_t wbase = sb + OFF_W + aoff;
    const int colb = w*16 + lanehi;

#define ALOAD(b, kh) do { \
    const uint32_t c32 = (uint32_t)(((kh)*3 + kw)*2 + half) * 32u; \
    ldm4(aA[b][0], wbase + c32); ldm4(aA[b][1], wbase + c32 + 16*WST*2); \
} while (0)

#define BLOAD(b, dd) do { \
    const int o = (s_[dd]*RC + colb + kw)*CIP + hoff + laneq2; \
    bB[b][0][0] = *reinterpret_cast<const uint32_t*>(xs16 + o); \
    bB[b][0][1] = *reinterpret_cast<const uint32_t*>(xs16 + o + 8); \
    bB[b][1][0] = *reinterpret_cast<const uint32_t*>(xs16 + o + 8*CIP); \
    bB[b][1][1] = *reinterpret_cast<const uint32_t*>(xs16 + o + 8*CIP + 8); \
} while (0)

#define MMA4(r, ab, bb) do { \
    mma_f16(acc[r][0][0], aA[ab][0], bB[bb][0]); \
    mma_f16(acc[r][1][0], aA[ab][1], bB[bb][0]); \
    mma_f16(acc[r][0][1], aA[ab][0], bB[bb][1]); \
    mma_f16(acc[r][1][1], aA[ab][1], bB[bb][1]); \
} while (0)

    #pragma unroll 1
    for (int t = 0; t < pairs; t++) {
        const int y = row0 + 2*t;
        int s_[4];
        #pragma unroll
        for (int dd = 0; dd < 4; dd++) s_[dd] = (y - 1 + dd) & (NSLOT - 1);

        float acc[2][2][2][4];
        #pragma unroll
        for (int r = 0; r < 2; r++)
            #pragma unroll
            for (int mi = 0; mi < 2; mi++)
                #pragma unroll
                for (int j = 0; j < 2; j++)
                    #pragma unroll
                    for (int q = 0; q < 4; q++) acc[r][mi][j][q] = 0.f;

        #pragma unroll 1
        for (int kwh = 0; kwh < 6; kwh++) {
            const int kw   = kwh >> 1;
            const int half = kwh & 1;
            const int hoff = half * 16;
            uint32_t aA[2][2][4];
            uint32_t bB[2][2][2];

            ALOAD(0, 0);                 // A: kh0
            BLOAD(0, 0);                 // B: d=-1
            ALOAD(1, 1);                 // A: kh1
            BLOAD(1, 1);                 // B: d=0
            MMA4(0, 0, 0);               // row0/kh0 @ d=-1
            BLOAD(0, 2);                 // B: d=1 (reuse buf0)
            MMA4(1, 0, 1);               // row1/kh0 @ d=0
            MMA4(0, 1, 1);               // row0/kh1 @ d=0
            ALOAD(0, 2);                 // A: kh2 (reuse abuf0)
            MMA4(1, 1, 0);               // row1/kh1 @ d=1
            BLOAD(1, 3);                 // B: d=2 (reuse buf1)
            MMA4(0, 0, 0);               // row0/kh2 @ d=1
            MMA4(1, 0, 1);               // row1/kh2 @ d=2
        }

        // ---- epilogue: 2 rows, bias + coalesced float2 stores ----
        #pragma unroll
        for (int r = 0; r < 2; r++) {
            const int yy = y + r;
            const int pxb = x0 + w*16 + laneq2;
            #pragma unroll
            for (int mi = 0; mi < 2; mi++) {
                const float bA = mi ? bias2 : bias0;
                const float bB2 = mi ? bias3 : bias1;
                const int coA = mi*16 + lanehi;
                float* o0 = out + (((size_t)n*COUT + coA)*HW + yy)*HW + pxb;
                #pragma unroll
                for (int j = 0; j < 2; j++) {
                    *reinterpret_cast<float2*>(o0 + 8*j) =
                        make_float2(acc[r][mi][j][0] + bA, acc[r][mi][j][1] + bA);
                    *reinterpret_cast<float2*>(o0 + 8*j + (size_t)8*HW*HW) =
                        make_float2(acc[r][mi][j][2] + bB2, acc[r][mi][j][3] + bB2);
                }
            }
        }

        if (t + 1 < pairs) {
            __syncthreads();
            // merged staging of rows y+3 and y+4, all LDGs batched
            stage_row(xn, xs32, y + 3, x0, tid);
            stage_row(xn, xs32, y + 4, x0, tid);
            __syncthreads();
        }
    }
#undef ALOAD
#undef BLOAD
#undef MMA4
}

// ---------------------------------------------------------------------------
extern "C" void kernel_launch(void* const* d_in, const int* in_sizes, int n_in,
                              void* d_out, int out_size)
{
    const float* x      = (const float*)d_in[0];
    const float* y      = (const float*)d_in[1];
    const float* weight = (const float*)d_in[2];
    const float* fc_w1  = (const float*)d_in[3];
    const float* fc_b1  = (const float*)d_in[4];
    const float* fc_a   = (const float*)d_in[5];
    const float* fc_w2  = (const float*)d_in[6];
    const float* fc_b2  = (const float*)d_in[7];
    const float* b_w1   = (const float*)d_in[8];
    const float* b_b1   = (const float*)d_in[9];
    const float* b_a    = (const float*)d_in[10];
    const float* b_w2   = (const float*)d_in[11];
    const float* b_b2   = (const float*)d_in[12];
    float* out = (float*)d_out;

    cudaFuncSetAttribute(conv_mma,
                         cudaFuncAttributeMaxDynamicSharedMemorySize,
                         CONV_SMEM);

    mlp_fused<<<577, 256>>>(y, weight, fc_w1, fc_b1, fc_a, fc_w2, fc_b2,
                            b_w1, b_b1, b_a, b_w2, b_b2);
    conv_mma<<<dim3(111, BN), 256, CONV_SMEM>>>(x, out);
}